// round 11
// baseline (speedup 1.0000x reference)
#include <cuda_runtime.h>
#include <cuda_bf16.h>
#include <cstdint>
#include <math.h>

// Problem constants
#define Bsz 2
#define Tsz 2048
#define NE 2048
#define NH 16
#define NKV 4
#define DH 128
#define GQ 4
#define QKV_W 3072          // NE + 2*NKV*DH
#define MROWS (Bsz*Tsz)     // 4096

// Scratch (allocation-free rule: __device__ globals)
__device__ float g_qkv[MROWS * QKV_W];   // ~50 MB
__device__ float g_y[MROWS * NE];        // ~34 MB

// ---------------------------------------------------------------------------
// fp32 SGEMM: C[M,N] = A[M,K] @ B[K,N], row-major.
// 128x128 tile, BK=8, 256 threads, 8x8 micro-tile.
// Double-buffered smem + register prefetch: one sync per K-chunk, LDG latency
// hidden behind the FFMA loop of the previous chunk.
// ---------------------------------------------------------------------------
#define BM 128
#define BN 128
#define BK 8
#define TM 8
#define TN 8

__global__ __launch_bounds__(256, 2)
void sgemm_kernel(const float* __restrict__ A, const float* __restrict__ B,
                  float* __restrict__ C, int M, int N, int K) {
    __shared__ float As[2][BK][BM];
    __shared__ float Bs[2][BK][BN];

    const int tid = threadIdx.x;
    const int bm = blockIdx.y * BM;
    const int bn = blockIdx.x * BN;

    const int tx = tid & 15;   // 0..15
    const int ty = tid >> 4;   // 0..15

    // global-load mapping
    const int a_row = tid >> 1;          // 0..127
    const int a_col = (tid & 1) * 4;     // 0 or 4
    const int b_row = tid >> 5;          // 0..7
    const int b_col = (tid & 31) * 4;    // 0..124

    float acc[TM][TN];
    #pragma unroll
    for (int i = 0; i < TM; i++)
        #pragma unroll
        for (int j = 0; j < TN; j++) acc[i][j] = 0.f;

    const float* Aptr = A + (size_t)(bm + a_row) * K + a_col;
    const float* Bptr = B + (size_t)b_row * N + bn + b_col;

    const int nch = K / BK;

    // prologue: chunk 0 -> buffer 0
    {
        float4 av = *(const float4*)(Aptr);
        As[0][a_col + 0][a_row] = av.x;
        As[0][a_col + 1][a_row] = av.y;
        As[0][a_col + 2][a_row] = av.z;
        As[0][a_col + 3][a_row] = av.w;
        *(float4*)&Bs[0][b_row][b_col] = *(const float4*)(Bptr);
    }
    __syncthreads();

    for (int ch = 0; ch < nch; ch++) {
        const int cur = ch & 1;
        float4 av, bv;
        const bool has_next = (ch + 1 < nch);
        if (has_next) {
            const int k0 = (ch + 1) * BK;
            av = *(const float4*)(Aptr + k0);
            bv = *(const float4*)(Bptr + (size_t)k0 * N);
        }

        #pragma unroll
        for (int kk = 0; kk < BK; kk++) {
            float4 a0 = *(const float4*)&As[cur][kk][ty * TM];
            float4 a1 = *(const float4*)&As[cur][kk][ty * TM + 4];
            float4 b0 = *(const float4*)&Bs[cur][kk][tx * TN];
            float4 b1 = *(const float4*)&Bs[cur][kk][tx * TN + 4];
            float ar[TM] = {a0.x, a0.y, a0.z, a0.w, a1.x, a1.y, a1.z, a1.w};
            float br[TN] = {b0.x, b0.y, b0.z, b0.w, b1.x, b1.y, b1.z, b1.w};
            #pragma unroll
            for (int i = 0; i < TM; i++)
                #pragma unroll
                for (int j = 0; j < TN; j++)
                    acc[i][j] += ar[i] * br[j];
        }

        if (has_next) {
            const int nxt = cur ^ 1;
            As[nxt][a_col + 0][a_row] = av.x;
            As[nxt][a_col + 1][a_row] = av.y;
            As[nxt][a_col + 2][a_row] = av.z;
            As[nxt][a_col + 3][a_row] = av.w;
            *(float4*)&Bs[nxt][b_row][b_col] = bv;
        }
        __syncthreads();
    }

    #pragma unroll
    for (int i = 0; i < TM; i++) {
        float* crow = C + (size_t)(bm + ty * TM + i) * N + bn + tx * TN;
        *(float4*)(crow + 0) = make_float4(acc[i][0], acc[i][1], acc[i][2], acc[i][3]);
        *(float4*)(crow + 4) = make_float4(acc[i][4], acc[i][5], acc[i][6], acc[i][7]);
    }
}

// ---------------------------------------------------------------------------
// YaRN RoPE applied in-place to Q and K inside g_qkv.
// ---------------------------------------------------------------------------
#define ATTN_FACTOR 1.4158883083359672f
#define LG2_BASE 19.931568569324174f   // log2(1e6)

__global__ void rope_kernel(float* __restrict__ qkv) {
    long long idx = (long long)blockIdx.x * blockDim.x + threadIdx.x;
    const long long total = (long long)MROWS * 20 * 64;
    if (idx >= total) return;

    int i   = (int)(idx & 63);
    int hd  = (int)((idx >> 6) % 20);
    long long bt = idx / (64 * 20);
    int t   = (int)(bt % Tsz);

    float fi = (float)i;
    float ramp = fminf(fmaxf((fi - 23.0f) * (1.0f / 8.0f), 0.0f), 1.0f);
    float extrap = 1.0f - ramp;
    float pf = exp2f(fi * (LG2_BASE / 64.0f));
    float inv = ramp * (1.0f / (64.0f * pf)) + extrap * (1.0f / pf);

    float angle = (float)t * inv;
    float c = cosf(angle);
    float s = sinf(angle);

    int col = (hd < 16) ? hd * DH : NE + (hd - 16) * DH;
    float* p = qkv + bt * QKV_W + col + 2 * i;
    float xe = p[0], xo = p[1];
    p[0] = (xe * c - xo * s) * ATTN_FACTOR;
    p[1] = (xe * s + xo * c) * ATTN_FACTOR;
}

// ---------------------------------------------------------------------------
// Flash attention (causal, GQA), tiled softmax.
// Block = 64 q rows x one (b,h). 256 threads: 4 threads/row, 32 dims each.
// Keys in 32-row tiles; alpha-rescale once per tile; P staged in smem.
// ---------------------------------------------------------------------------
#define AT_ROWS 64
#define AT_KT 32
#define SCALE_L2 (0.08838834764831843f * 1.4426950408889634f)   // (1/sqrt(128))*log2(e)

__global__ __launch_bounds__(256, 2)
void flash_attn_kernel(const float* __restrict__ qkv, float* __restrict__ y) {
    __shared__ float Ks[AT_KT][DH];
    __shared__ float Vs[AT_KT][DH];
    __shared__ float Ps[AT_ROWS][AT_KT + 1];

    const int qt = blockIdx.x;
    const int bh = blockIdx.y;
    const int b  = bh >> 4;
    const int hh = bh & 15;
    const int kvh = hh >> 2;

    const int tid = threadIdx.x;
    const int row = tid >> 2;          // 0..63
    const int qlane = tid & 3;         // 0..3
    const int qrow = qt * AT_ROWS + row;
    const int dbase = qlane * 32;

    const float* Qp = qkv + ((size_t)(b * Tsz + qrow)) * QKV_W + hh * DH + dbase;
    const float* Kbase = qkv + (size_t)b * Tsz * QKV_W + NE + kvh * DH;
    const float* Vbase = Kbase + NKV * DH;

    float q[32];
    #pragma unroll
    for (int d = 0; d < 32; d++) q[d] = Qp[d] * SCALE_L2;   // fold scale*log2e into q

    float acc[32];
    #pragma unroll
    for (int d = 0; d < 32; d++) acc[d] = 0.f;
    float m = -1e30f, l = 0.f;

    const int ntiles = (qt + 1) * (AT_ROWS / AT_KT);

    for (int t0 = 0; t0 < ntiles; t0++) {
        const int k0 = t0 * AT_KT;
        __syncthreads();
        #pragma unroll
        for (int i = tid; i < AT_KT * DH / 4; i += 256) {
            int r = i >> 5, c = (i & 31) * 4;
            *(float4*)&Ks[r][c] = *(const float4*)&Kbase[(size_t)(k0 + r) * QKV_W + c];
            *(float4*)&Vs[r][c] = *(const float4*)&Vbase[(size_t)(k0 + r) * QKV_W + c];
        }
        __syncthreads();

        float pl[8];
        float tmax = -1e30f;
        #pragma unroll
        for (int j = 0; j < AT_KT; j++) {
            const float4* kr = (const float4*)&Ks[j][dbase];
            float s = 0.f;
            #pragma unroll
            for (int d4 = 0; d4 < 8; d4++) {
                float4 kv = kr[d4];
                s += q[d4 * 4 + 0] * kv.x + q[d4 * 4 + 1] * kv.y
                   + q[d4 * 4 + 2] * kv.z + q[d4 * 4 + 3] * kv.w;
            }
            s += __shfl_xor_sync(0xffffffffu, s, 1);
            s += __shfl_xor_sync(0xffffffffu, s, 2);
            if (k0 + j > qrow) s = -1e30f;
            tmax = fmaxf(tmax, s);
            if ((j & 3) == qlane) pl[j >> 2] = s;
        }
        float m_new = fmaxf(m, tmax);
        float alpha = exp2f(m - m_new);
        float lsum = 0.f;
        #pragma unroll
        for (int jj = 0; jj < 8; jj++) {
            pl[jj] = exp2f(pl[jj] - m_new);
            lsum += pl[jj];
        }
        lsum += __shfl_xor_sync(0xffffffffu, lsum, 1);
        lsum += __shfl_xor_sync(0xffffffffu, lsum, 2);
        l = l * alpha + lsum;
        m = m_new;
        #pragma unroll
        for (int jj = 0; jj < 8; jj++) Ps[row][jj * 4 + qlane] = pl[jj];
        #pragma unroll
        for (int d = 0; d < 32; d++) acc[d] *= alpha;
        __syncwarp();

        #pragma unroll
        for (int j = 0; j < AT_KT; j++) {
            float pj = Ps[row][j];
            const float4* vr = (const float4*)&Vs[j][dbase];
            #pragma unroll
            for (int d4 = 0; d4 < 8; d4++) {
                float4 vv = vr[d4];
                acc[d4 * 4 + 0] += pj * vv.x;
                acc[d4 * 4 + 1] += pj * vv.y;
                acc[d4 * 4 + 2] += pj * vv.z;
                acc[d4 * 4 + 3] += pj * vv.w;
            }
        }
    }

    float inv_l = 1.0f / l;
    float* yp = y + ((size_t)(b * Tsz + qrow)) * NE + hh * DH + dbase;
    #pragma unroll
    for (int d4 = 0; d4 < 8; d4++) {
        *(float4*)(yp + d4 * 4) = make_float4(acc[d4 * 4 + 0] * inv_l, acc[d4 * 4 + 1] * inv_l,
                                              acc[d4 * 4 + 2] * inv_l, acc[d4 * 4 + 3] * inv_l);
    }
}

// ---------------------------------------------------------------------------
// Launch
// ---------------------------------------------------------------------------
extern "C" void kernel_launch(void* const* d_in, const int* in_sizes, int n_in,
                              void* d_out, int out_size) {
    const float* x     = (const float*)d_in[0];
    const float* w_qkv = (const float*)d_in[1];
    const float* w_o   = (const float*)d_in[2];
    float* out = (float*)d_out;

    float* qkv = nullptr;
    float* y   = nullptr;
    cudaGetSymbolAddress((void**)&qkv, g_qkv);
    cudaGetSymbolAddress((void**)&y,   g_y);

    // 1) QKV projection: [4096,2048] @ [2048,3072]
    {
        dim3 grid(QKV_W / BN, MROWS / BM);
        sgemm_kernel<<<grid, 256>>>(x, w_qkv, qkv, MROWS, QKV_W, NE);
    }

    // 2) RoPE on Q and K (in place)
    {
        long long total = (long long)MROWS * 20 * 64;
        rope_kernel<<<(int)((total + 255) / 256), 256>>>(qkv);
    }

    // 3) Causal GQA flash attention -> y [4096, 2048]
    {
        dim3 grid(Tsz / AT_ROWS, Bsz * NH);
        flash_attn_kernel<<<grid, 256>>>(qkv, y);
    }

    // 4) Output projection: [4096,2048] @ [2048,2048] -> out
    {
        dim3 grid(NE / BN, MROWS / BM);
        sgemm_kernel<<<grid, 256>>>(y, w_o, out, MROWS, NE, NE);
    }
}

// round 13
// speedup vs baseline: 1.6652x; 1.6652x over previous
#include <cuda_runtime.h>
#include <cuda_bf16.h>
#include <cstdint>
#include <math.h>

// Problem constants
#define Bsz 2
#define Tsz 2048
#define NE 2048
#define NH 16
#define NKV 4
#define DH 128
#define GQ 4
#define QKV_W 3072          // NE + 2*NKV*DH
#define MROWS (Bsz*Tsz)     // 4096

// Scratch (allocation-free rule: __device__ globals)
__device__ float g_qkv[MROWS * QKV_W];   // ~50 MB
__device__ float g_y[MROWS * NE];        // ~34 MB
__device__ float g_at[(size_t)NE * MROWS]; // 33.5 MB: transposed activations [K][M]

// ---------------------------------------------------------------------------
// Helpers
// ---------------------------------------------------------------------------
__device__ __forceinline__ uint32_t smem_u32(const void* p) {
    uint32_t a;
    asm("{ .reg .u64 t; cvta.to.shared.u64 t, %1; cvt.u32.u64 %0, t; }" : "=r"(a) : "l"(p));
    return a;
}
__device__ __forceinline__ void cpa16(uint32_t dst, const void* src) {
    asm volatile("cp.async.cg.shared.global [%0], [%1], 16;" :: "r"(dst), "l"(src));
}
#define CP_COMMIT() asm volatile("cp.async.commit_group;" ::: "memory")
#define CP_WAIT2()  asm volatile("cp.async.wait_group 2;" ::: "memory")

// ---------------------------------------------------------------------------
// Transpose: X [M][K] -> XT [K][M]  (fp32, 32x32 tiles)
// ---------------------------------------------------------------------------
__global__ void transpose_kernel(const float* __restrict__ X, float* __restrict__ XT,
                                 int M, int K) {
    __shared__ float t[32][33];
    const int bx = blockIdx.x * 32;   // K tile
    const int by = blockIdx.y * 32;   // M tile
    const int tx = threadIdx.x;       // 0..31
    const int ty0 = threadIdx.y;      // 0..7
    #pragma unroll
    for (int i = 0; i < 4; i++) {
        int ty = ty0 + i * 8;
        t[ty][tx] = X[(size_t)(by + ty) * K + bx + tx];
    }
    __syncthreads();
    #pragma unroll
    for (int i = 0; i < 4; i++) {
        int ty = ty0 + i * 8;
        XT[(size_t)(bx + ty) * M + by + tx] = t[tx][ty];
    }
}

// ---------------------------------------------------------------------------
// fp32 SGEMM with transposed A: C[M,N] = At[K,M]^T @ B[K,N], row-major.
// 128x128 tile, BK=8, 256 threads, 8x8 micro-tile.
// 4-stage cp.async pipeline: loads go straight to smem (no register cost),
// one __syncthreads per K-chunk, inner FFMA loop identical to the proven R1 loop.
// ---------------------------------------------------------------------------
#define BM 128
#define BN 128
#define BK 8
#define TM 8
#define TN 8
#define STAGES 4

__global__ __launch_bounds__(256)
void sgemm_at(const float* __restrict__ At, const float* __restrict__ B,
              float* __restrict__ C, int M, int N, int K) {
    __shared__ float As[STAGES][BK][BM];   // 16 KB
    __shared__ float Bs[STAGES][BK][BN];   // 16 KB

    const int tid = threadIdx.x;
    const int bm = blockIdx.y * BM;
    const int bn = blockIdx.x * BN;

    const int tx = tid & 15;   // 0..15
    const int ty = tid >> 4;   // 0..15

    // load mapping: one 16B cp.async per tile per thread
    const int l_row = tid >> 5;          // 0..7  (k within chunk)
    const int l_col = (tid & 31) * 4;    // 0..124

    const float* Aptr = At + (size_t)l_row * M + bm + l_col;  // + k0*M
    const float* Bptr = B + (size_t)l_row * N + bn + l_col;   // + k0*N

    float acc[TM][TN];
    #pragma unroll
    for (int i = 0; i < TM; i++)
        #pragma unroll
        for (int j = 0; j < TN; j++) acc[i][j] = 0.f;

    const int nch = K / BK;

    // prologue: stages 0..2
    #pragma unroll
    for (int s = 0; s < STAGES - 1; s++) {
        const size_t k0 = (size_t)s * BK;
        cpa16(smem_u32(&As[s][l_row][l_col]), Aptr + k0 * M);
        cpa16(smem_u32(&Bs[s][l_row][l_col]), Bptr + k0 * N);
        CP_COMMIT();
    }

    for (int ch = 0; ch < nch; ch++) {
        CP_WAIT2();
        __syncthreads();

        const int cur = ch & (STAGES - 1);
        #pragma unroll
        for (int kk = 0; kk < BK; kk++) {
            float4 a0 = *(const float4*)&As[cur][kk][ty * TM];
            float4 a1 = *(const float4*)&As[cur][kk][ty * TM + 4];
            float4 b0 = *(const float4*)&Bs[cur][kk][tx * TN];
            float4 b1 = *(const float4*)&Bs[cur][kk][tx * TN + 4];
            float ar[TM] = {a0.x, a0.y, a0.z, a0.w, a1.x, a1.y, a1.z, a1.w};
            float br[TN] = {b0.x, b0.y, b0.z, b0.w, b1.x, b1.y, b1.z, b1.w};
            #pragma unroll
            for (int i = 0; i < TM; i++)
                #pragma unroll
                for (int j = 0; j < TN; j++)
                    acc[i][j] += ar[i] * br[j];
        }

        const int nx = ch + STAGES - 1;
        if (nx < nch) {
            const int st = nx & (STAGES - 1);
            const size_t k0 = (size_t)nx * BK;
            cpa16(smem_u32(&As[st][l_row][l_col]), Aptr + k0 * M);
            cpa16(smem_u32(&Bs[st][l_row][l_col]), Bptr + k0 * N);
        }
        CP_COMMIT();
    }

    #pragma unroll
    for (int i = 0; i < TM; i++) {
        float* crow = C + (size_t)(bm + ty * TM + i) * N + bn + tx * TN;
        *(float4*)(crow + 0) = make_float4(acc[i][0], acc[i][1], acc[i][2], acc[i][3]);
        *(float4*)(crow + 4) = make_float4(acc[i][4], acc[i][5], acc[i][6], acc[i][7]);
    }
}

// ---------------------------------------------------------------------------
// YaRN RoPE applied in-place to Q and K inside g_qkv.
// ---------------------------------------------------------------------------
#define ATTN_FACTOR 1.4158883083359672f
#define LG2_BASE 19.931568569324174f   // log2(1e6)

__global__ void rope_kernel(float* __restrict__ qkv) {
    long long idx = (long long)blockIdx.x * blockDim.x + threadIdx.x;
    const long long total = (long long)MROWS * 20 * 64;
    if (idx >= total) return;

    int i   = (int)(idx & 63);
    int hd  = (int)((idx >> 6) % 20);
    long long bt = idx / (64 * 20);
    int t   = (int)(bt % Tsz);

    float fi = (float)i;
    float ramp = fminf(fmaxf((fi - 23.0f) * (1.0f / 8.0f), 0.0f), 1.0f);
    float extrap = 1.0f - ramp;
    float pf = exp2f(fi * (LG2_BASE / 64.0f));
    float inv = ramp * (1.0f / (64.0f * pf)) + extrap * (1.0f / pf);

    float angle = (float)t * inv;
    float c = cosf(angle);
    float s = sinf(angle);

    int col = (hd < 16) ? hd * DH : NE + (hd - 16) * DH;
    float* p = qkv + bt * QKV_W + col + 2 * i;
    float xe = p[0], xo = p[1];
    p[0] = (xe * c - xo * s) * ATTN_FACTOR;
    p[1] = (xe * s + xo * c) * ATTN_FACTOR;
}

// ---------------------------------------------------------------------------
// Flash attention (causal, GQA), tiled softmax.
// Block = 64 q rows x one (b,h). 256 threads: 4 threads/row, 32 dims each.
// Keys in 32-row tiles; alpha-rescale once per tile; P staged in smem.
// ---------------------------------------------------------------------------
#define AT_ROWS 64
#define AT_KT 32
#define SCALE_L2 (0.08838834764831843f * 1.4426950408889634f)   // (1/sqrt(128))*log2(e)

__global__ __launch_bounds__(256, 2)
void flash_attn_kernel(const float* __restrict__ qkv, float* __restrict__ y) {
    __shared__ float Ks[AT_KT][DH];
    __shared__ float Vs[AT_KT][DH];
    __shared__ float Ps[AT_ROWS][AT_KT + 1];

    const int qt = blockIdx.x;
    const int bh = blockIdx.y;
    const int b  = bh >> 4;
    const int hh = bh & 15;
    const int kvh = hh >> 2;

    const int tid = threadIdx.x;
    const int row = tid >> 2;          // 0..63
    const int qlane = tid & 3;         // 0..3
    const int qrow = qt * AT_ROWS + row;
    const int dbase = qlane * 32;

    const float* Qp = qkv + ((size_t)(b * Tsz + qrow)) * QKV_W + hh * DH + dbase;
    const float* Kbase = qkv + (size_t)b * Tsz * QKV_W + NE + kvh * DH;
    const float* Vbase = Kbase + NKV * DH;

    float q[32];
    #pragma unroll
    for (int d = 0; d < 32; d++) q[d] = Qp[d] * SCALE_L2;   // fold scale*log2e into q

    float acc[32];
    #pragma unroll
    for (int d = 0; d < 32; d++) acc[d] = 0.f;
    float m = -1e30f, l = 0.f;

    const int ntiles = (qt + 1) * (AT_ROWS / AT_KT);

    for (int t0 = 0; t0 < ntiles; t0++) {
        const int k0 = t0 * AT_KT;
        __syncthreads();
        #pragma unroll
        for (int i = tid; i < AT_KT * DH / 4; i += 256) {
            int r = i >> 5, c = (i & 31) * 4;
            *(float4*)&Ks[r][c] = *(const float4*)&Kbase[(size_t)(k0 + r) * QKV_W + c];
            *(float4*)&Vs[r][c] = *(const float4*)&Vbase[(size_t)(k0 + r) * QKV_W + c];
        }
        __syncthreads();

        float pl[8];
        float tmax = -1e30f;
        #pragma unroll
        for (int j = 0; j < AT_KT; j++) {
            const float4* kr = (const float4*)&Ks[j][dbase];
            float s = 0.f;
            #pragma unroll
            for (int d4 = 0; d4 < 8; d4++) {
                float4 kv = kr[d4];
                s += q[d4 * 4 + 0] * kv.x + q[d4 * 4 + 1] * kv.y
                   + q[d4 * 4 + 2] * kv.z + q[d4 * 4 + 3] * kv.w;
            }
            s += __shfl_xor_sync(0xffffffffu, s, 1);
            s += __shfl_xor_sync(0xffffffffu, s, 2);
            if (k0 + j > qrow) s = -1e30f;
            tmax = fmaxf(tmax, s);
            if ((j & 3) == qlane) pl[j >> 2] = s;
        }
        float m_new = fmaxf(m, tmax);
        float alpha = exp2f(m - m_new);
        float lsum = 0.f;
        #pragma unroll
        for (int jj = 0; jj < 8; jj++) {
            pl[jj] = exp2f(pl[jj] - m_new);
            lsum += pl[jj];
        }
        lsum += __shfl_xor_sync(0xffffffffu, lsum, 1);
        lsum += __shfl_xor_sync(0xffffffffu, lsum, 2);
        l = l * alpha + lsum;
        m = m_new;
        #pragma unroll
        for (int jj = 0; jj < 8; jj++) Ps[row][jj * 4 + qlane] = pl[jj];
        #pragma unroll
        for (int d = 0; d < 32; d++) acc[d] *= alpha;
        __syncwarp();

        #pragma unroll
        for (int j = 0; j < AT_KT; j++) {
            float pj = Ps[row][j];
            const float4* vr = (const float4*)&Vs[j][dbase];
            #pragma unroll
            for (int d4 = 0; d4 < 8; d4++) {
                float4 vv = vr[d4];
                acc[d4 * 4 + 0] += pj * vv.x;
                acc[d4 * 4 + 1] += pj * vv.y;
                acc[d4 * 4 + 2] += pj * vv.z;
                acc[d4 * 4 + 3] += pj * vv.w;
            }
        }
    }

    float inv_l = 1.0f / l;
    float* yp = y + ((size_t)(b * Tsz + qrow)) * NE + hh * DH + dbase;
    #pragma unroll
    for (int d4 = 0; d4 < 8; d4++) {
        *(float4*)(yp + d4 * 4) = make_float4(acc[d4 * 4 + 0] * inv_l, acc[d4 * 4 + 1] * inv_l,
                                              acc[d4 * 4 + 2] * inv_l, acc[d4 * 4 + 3] * inv_l);
    }
}

// ---------------------------------------------------------------------------
// Launch
// ---------------------------------------------------------------------------
extern "C" void kernel_launch(void* const* d_in, const int* in_sizes, int n_in,
                              void* d_out, int out_size) {
    const float* x     = (const float*)d_in[0];
    const float* w_qkv = (const float*)d_in[1];
    const float* w_o   = (const float*)d_in[2];
    float* out = (float*)d_out;

    float* qkv = nullptr;
    float* y   = nullptr;
    float* at  = nullptr;
    cudaGetSymbolAddress((void**)&qkv, g_qkv);
    cudaGetSymbolAddress((void**)&y,   g_y);
    cudaGetSymbolAddress((void**)&at,  g_at);

    // 1) Transpose x -> at [NE][MROWS], then QKV projection via cp.async SGEMM
    {
        dim3 gT(NE / 32, MROWS / 32);
        transpose_kernel<<<gT, dim3(32, 8)>>>(x, at, MROWS, NE);
        dim3 grid(QKV_W / BN, MROWS / BM);
        sgemm_at<<<grid, 256>>>(at, w_qkv, qkv, MROWS, QKV_W, NE);
    }

    // 2) RoPE on Q and K (in place)
    {
        long long total = (long long)MROWS * 20 * 64;
        rope_kernel<<<(int)((total + 255) / 256), 256>>>(qkv);
    }

    // 3) Causal GQA flash attention -> y [4096, 2048]
    {
        dim3 grid(Tsz / AT_ROWS, Bsz * NH);
        flash_attn_kernel<<<grid, 256>>>(qkv, y);
    }

    // 4) Transpose y -> at, then output projection -> out
    {
        dim3 gT(NE / 32, MROWS / 32);
        transpose_kernel<<<gT, dim3(32, 8)>>>(y, at, MROWS, NE);
        dim3 grid(NE / BN, MROWS / BM);
        sgemm_at<<<grid, 256>>>(at, w_o, out, MROWS, NE, NE);
    }
}

// round 14
// speedup vs baseline: 4.1640x; 2.5006x over previous
#include <cuda_runtime.h>
#include <cuda_bf16.h>
#include <cstdint>
#include <math.h>

// Problem constants
#define Bsz 2
#define Tsz 2048
#define NE 2048
#define NH 16
#define NKV 4
#define DH 128
#define GQ 4
#define QKV_W 3072          // NE + 2*NKV*DH
#define MROWS (Bsz*Tsz)     // 4096

// Scratch (allocation-free rule: __device__ globals)
__device__ float g_qkv[MROWS * QKV_W];   // ~50 MB
__device__ float g_y[MROWS * NE];        // ~34 MB
__device__ float g_at[(size_t)NE * MROWS]; // 33.5 MB: transposed activations [K][M]

// ---------------------------------------------------------------------------
// Helpers
// ---------------------------------------------------------------------------
__device__ __forceinline__ uint32_t smem_u32(const void* p) {
    uint32_t a;
    asm("{ .reg .u64 t; cvta.to.shared.u64 t, %1; cvt.u32.u64 %0, t; }" : "=r"(a) : "l"(p));
    return a;
}
__device__ __forceinline__ void cpa16(uint32_t dst, const void* src) {
    asm volatile("cp.async.cg.shared.global [%0], [%1], 16;" :: "r"(dst), "l"(src));
}
#define CP_COMMIT() asm volatile("cp.async.commit_group;" ::: "memory")
#define CP_WAIT2()  asm volatile("cp.async.wait_group 2;" ::: "memory")

// ---------------------------------------------------------------------------
// Transpose: X [M][K] -> XT [K][M]  (fp32, 32x32 tiles)
// ---------------------------------------------------------------------------
__global__ void transpose_kernel(const float* __restrict__ X, float* __restrict__ XT,
                                 int M, int K) {
    __shared__ float t[32][33];
    const int bx = blockIdx.x * 32;   // K tile
    const int by = blockIdx.y * 32;   // M tile
    const int tx = threadIdx.x;       // 0..31
    const int ty0 = threadIdx.y;      // 0..7
    #pragma unroll
    for (int i = 0; i < 4; i++) {
        int ty = ty0 + i * 8;
        t[ty][tx] = X[(size_t)(by + ty) * K + bx + tx];
    }
    __syncthreads();
    #pragma unroll
    for (int i = 0; i < 4; i++) {
        int ty = ty0 + i * 8;
        XT[(size_t)(bx + ty) * M + by + tx] = t[tx][ty];
    }
}

// ---------------------------------------------------------------------------
// fp32 SGEMM with transposed A: C[M,N] = At[K,M]^T @ B[K,N], row-major.
// 128x128 tile, BK=8, 256 threads, 8x8 micro-tile, 4-stage cp.async pipeline.
// ---------------------------------------------------------------------------
#define BM 128
#define BN 128
#define BK 8
#define TM 8
#define TN 8
#define STAGES 4

__global__ __launch_bounds__(256)
void sgemm_at(const float* __restrict__ At, const float* __restrict__ B,
              float* __restrict__ C, int M, int N, int K) {
    __shared__ float As[STAGES][BK][BM];   // 16 KB
    __shared__ float Bs[STAGES][BK][BN];   // 16 KB

    const int tid = threadIdx.x;
    const int bm = blockIdx.y * BM;
    const int bn = blockIdx.x * BN;

    const int tx = tid & 15;   // 0..15
    const int ty = tid >> 4;   // 0..15

    // load mapping: one 16B cp.async per tile per thread
    const int l_row = tid >> 5;          // 0..7  (k within chunk)
    const int l_col = (tid & 31) * 4;    // 0..124

    const float* Aptr = At + (size_t)l_row * M + bm + l_col;  // + k0*M
    const float* Bptr = B + (size_t)l_row * N + bn + l_col;   // + k0*N

    float acc[TM][TN];
    #pragma unroll
    for (int i = 0; i < TM; i++)
        #pragma unroll
        for (int j = 0; j < TN; j++) acc[i][j] = 0.f;

    const int nch = K / BK;

    // prologue: stages 0..2
    #pragma unroll
    for (int s = 0; s < STAGES - 1; s++) {
        const size_t k0 = (size_t)s * BK;
        cpa16(smem_u32(&As[s][l_row][l_col]), Aptr + k0 * M);
        cpa16(smem_u32(&Bs[s][l_row][l_col]), Bptr + k0 * N);
        CP_COMMIT();
    }

    for (int ch = 0; ch < nch; ch++) {
        CP_WAIT2();
        __syncthreads();

        const int cur = ch & (STAGES - 1);
        #pragma unroll
        for (int kk = 0; kk < BK; kk++) {
            float4 a0 = *(const float4*)&As[cur][kk][ty * TM];
            float4 a1 = *(const float4*)&As[cur][kk][ty * TM + 4];
            float4 b0 = *(const float4*)&Bs[cur][kk][tx * TN];
            float4 b1 = *(const float4*)&Bs[cur][kk][tx * TN + 4];
            float ar[TM] = {a0.x, a0.y, a0.z, a0.w, a1.x, a1.y, a1.z, a1.w};
            float br[TN] = {b0.x, b0.y, b0.z, b0.w, b1.x, b1.y, b1.z, b1.w};
            #pragma unroll
            for (int i = 0; i < TM; i++)
                #pragma unroll
                for (int j = 0; j < TN; j++)
                    acc[i][j] += ar[i] * br[j];
        }

        const int nx = ch + STAGES - 1;
        if (nx < nch) {
            const int st = nx & (STAGES - 1);
            const size_t k0 = (size_t)nx * BK;
            cpa16(smem_u32(&As[st][l_row][l_col]), Aptr + k0 * M);
            cpa16(smem_u32(&Bs[st][l_row][l_col]), Bptr + k0 * N);
        }
        CP_COMMIT();
    }

    #pragma unroll
    for (int i = 0; i < TM; i++) {
        float* crow = C + (size_t)(bm + ty * TM + i) * N + bn + tx * TN;
        *(float4*)(crow + 0) = make_float4(acc[i][0], acc[i][1], acc[i][2], acc[i][3]);
        *(float4*)(crow + 4) = make_float4(acc[i][4], acc[i][5], acc[i][6], acc[i][7]);
    }
}

// ---------------------------------------------------------------------------
// YaRN RoPE applied in-place to Q and K inside g_qkv.
// ---------------------------------------------------------------------------
#define ATTN_FACTOR 1.4158883083359672f
#define LG2_BASE 19.931568569324174f   // log2(1e6)

__global__ void rope_kernel(float* __restrict__ qkv) {
    long long idx = (long long)blockIdx.x * blockDim.x + threadIdx.x;
    const long long total = (long long)MROWS * 20 * 64;
    if (idx >= total) return;

    int i   = (int)(idx & 63);
    int hd  = (int)((idx >> 6) % 20);
    long long bt = idx / (64 * 20);
    int t   = (int)(bt % Tsz);

    float fi = (float)i;
    float ramp = fminf(fmaxf((fi - 23.0f) * (1.0f / 8.0f), 0.0f), 1.0f);
    float extrap = 1.0f - ramp;
    float pf = exp2f(fi * (LG2_BASE / 64.0f));
    float inv = ramp * (1.0f / (64.0f * pf)) + extrap * (1.0f / pf);

    float angle = (float)t * inv;
    float c = cosf(angle);
    float s = sinf(angle);

    int col = (hd < 16) ? hd * DH : NE + (hd - 16) * DH;
    float* p = qkv + bt * QKV_W + col + 2 * i;
    float xe = p[0], xo = p[1];
    p[0] = (xe * c - xo * s) * ATTN_FACTOR;
    p[1] = (xe * s + xo * c) * ATTN_FACTOR;
}

// ---------------------------------------------------------------------------
// Flash attention (causal, GQA), tiled softmax.
// Block = 64 q rows x one (b,h). 256 threads: 4 threads/row.
// INTERLEAVED dim mapping: lane qlane owns dims {qlane*4 + 16*k + j}, so a
// quad's LDS.128s are 16B-consecutive (conflict-free) and the 8 rows sharing
// a warp broadcast the same Ks/Vs address. Smem rows padded to DH+4.
// ---------------------------------------------------------------------------
#define AT_ROWS 64
#define AT_KT 32
#define DHP (DH + 4)
#define SCALE_L2 (0.08838834764831843f * 1.4426950408889634f)   // (1/sqrt(128))*log2(e)

__global__ __launch_bounds__(256, 2)
void flash_attn_kernel(const float* __restrict__ qkv, float* __restrict__ y) {
    __shared__ float Ks[AT_KT][DHP];
    __shared__ float Vs[AT_KT][DHP];
    __shared__ float Ps[AT_ROWS][AT_KT + 1];

    const int qt = blockIdx.x;
    const int bh = blockIdx.y;
    const int b  = bh >> 4;
    const int hh = bh & 15;
    const int kvh = hh >> 2;

    const int tid = threadIdx.x;
    const int row = tid >> 2;          // 0..63
    const int qlane = tid & 3;         // 0..3
    const int qrow = qt * AT_ROWS + row;

    const float* Qp = qkv + ((size_t)(b * Tsz + qrow)) * QKV_W + hh * DH;
    const float* Kbase = qkv + (size_t)b * Tsz * QKV_W + NE + kvh * DH;
    const float* Vbase = Kbase + NKV * DH;

    // q[d4*4+jj] holds dim (qlane*4 + d4*16 + jj), scale*log2e folded in
    float q[32];
    #pragma unroll
    for (int d4 = 0; d4 < 8; d4++) {
        float4 v = *(const float4*)&Qp[qlane * 4 + d4 * 16];
        q[d4 * 4 + 0] = v.x * SCALE_L2;
        q[d4 * 4 + 1] = v.y * SCALE_L2;
        q[d4 * 4 + 2] = v.z * SCALE_L2;
        q[d4 * 4 + 3] = v.w * SCALE_L2;
    }

    float acc[32];
    #pragma unroll
    for (int d = 0; d < 32; d++) acc[d] = 0.f;
    float m = -1e30f, l = 0.f;

    const int ntiles = (qt + 1) * (AT_ROWS / AT_KT);

    for (int t0 = 0; t0 < ntiles; t0++) {
        const int k0 = t0 * AT_KT;
        __syncthreads();
        #pragma unroll
        for (int i = tid; i < AT_KT * DH / 4; i += 256) {
            int r = i >> 5, c = (i & 31) * 4;
            *(float4*)&Ks[r][c] = *(const float4*)&Kbase[(size_t)(k0 + r) * QKV_W + c];
            *(float4*)&Vs[r][c] = *(const float4*)&Vbase[(size_t)(k0 + r) * QKV_W + c];
        }
        __syncthreads();

        float pl[8];
        float tmax = -1e30f;
        #pragma unroll
        for (int j = 0; j < AT_KT; j++) {
            const float4* kr = (const float4*)&Ks[j][qlane * 4];
            float s = 0.f;
            #pragma unroll
            for (int d4 = 0; d4 < 8; d4++) {
                float4 kv = kr[d4 * 4];          // &Ks[j][qlane*4 + d4*16]
                s += q[d4 * 4 + 0] * kv.x + q[d4 * 4 + 1] * kv.y
                   + q[d4 * 4 + 2] * kv.z + q[d4 * 4 + 3] * kv.w;
            }
            s += __shfl_xor_sync(0xffffffffu, s, 1);
            s += __shfl_xor_sync(0xffffffffu, s, 2);
            if (k0 + j > qrow) s = -1e30f;
            tmax = fmaxf(tmax, s);
            if ((j & 3) == qlane) pl[j >> 2] = s;
        }
        float m_new = fmaxf(m, tmax);
        float alpha = exp2f(m - m_new);
        float lsum = 0.f;
        #pragma unroll
        for (int jj = 0; jj < 8; jj++) {
            pl[jj] = exp2f(pl[jj] - m_new);
            lsum += pl[jj];
        }
        lsum += __shfl_xor_sync(0xffffffffu, lsum, 1);
        lsum += __shfl_xor_sync(0xffffffffu, lsum, 2);
        l = l * alpha + lsum;
        m = m_new;
        #pragma unroll
        for (int jj = 0; jj < 8; jj++) Ps[row][jj * 4 + qlane] = pl[jj];
        #pragma unroll
        for (int d = 0; d < 32; d++) acc[d] *= alpha;
        __syncwarp();

        #pragma unroll
        for (int j = 0; j < AT_KT; j++) {
            float pj = Ps[row][j];
            const float4* vr = (const float4*)&Vs[j][qlane * 4];
            #pragma unroll
            for (int d4 = 0; d4 < 8; d4++) {
                float4 vv = vr[d4 * 4];          // &Vs[j][qlane*4 + d4*16]
                acc[d4 * 4 + 0] += pj * vv.x;
                acc[d4 * 4 + 1] += pj * vv.y;
                acc[d4 * 4 + 2] += pj * vv.z;
                acc[d4 * 4 + 3] += pj * vv.w;
            }
        }
    }

    float inv_l = 1.0f / l;
    float* yp = y + ((size_t)(b * Tsz + qrow)) * NE + hh * DH;
    #pragma unroll
    for (int d4 = 0; d4 < 8; d4++) {
        *(float4*)(yp + qlane * 4 + d4 * 16) =
            make_float4(acc[d4 * 4 + 0] * inv_l, acc[d4 * 4 + 1] * inv_l,
                        acc[d4 * 4 + 2] * inv_l, acc[d4 * 4 + 3] * inv_l);
    }
}

// ---------------------------------------------------------------------------
// Launch
// ---------------------------------------------------------------------------
extern "C" void kernel_launch(void* const* d_in, const int* in_sizes, int n_in,
                              void* d_out, int out_size) {
    const float* x     = (const float*)d_in[0];
    const float* w_qkv = (const float*)d_in[1];
    const float* w_o   = (const float*)d_in[2];
    float* out = (float*)d_out;

    float* qkv = nullptr;
    float* y   = nullptr;
    float* at  = nullptr;
    cudaGetSymbolAddress((void**)&qkv, g_qkv);
    cudaGetSymbolAddress((void**)&y,   g_y);
    cudaGetSymbolAddress((void**)&at,  g_at);

    // 1) Transpose x -> at [NE][MROWS], then QKV projection via cp.async SGEMM
    {
        dim3 gT(NE / 32, MROWS / 32);
        transpose_kernel<<<gT, dim3(32, 8)>>>(x, at, MROWS, NE);
        dim3 grid(QKV_W / BN, MROWS / BM);
        sgemm_at<<<grid, 256>>>(at, w_qkv, qkv, MROWS, QKV_W, NE);
    }

    // 2) RoPE on Q and K (in place)
    {
        long long total = (long long)MROWS * 20 * 64;
        rope_kernel<<<(int)((total + 255) / 256), 256>>>(qkv);
    }

    // 3) Causal GQA flash attention -> y [4096, 2048]
    {
        dim3 grid(Tsz / AT_ROWS, Bsz * NH);
        flash_attn_kernel<<<grid, 256>>>(qkv, y);
    }

    // 4) Transpose y -> at, then output projection -> out
    {
        dim3 gT(NE / 32, MROWS / 32);
        transpose_kernel<<<gT, dim3(32, 8)>>>(y, at, MROWS, NE);
        dim3 grid(NE / BN, MROWS / BM);
        sgemm_at<<<grid, 256>>>(at, w_o, out, MROWS, NE, NE);
    }
}